// round 13
// baseline (speedup 1.0000x reference)
#include <cuda_runtime.h>
#include <cuda_fp16.h>
#include <math.h>

#define NMAX 50048
#define EMAX 1700000
#define CPAD 8     // cursor padding: 1 int per 32B sector
#define BCAP 128   // bucket capacity per node (deg ~ Poisson(32); 17 sigma)

// ---------------- scratch (device globals) ----------------------------------
__device__ __half g_tb[(size_t)NMAX * 128];  // t = x@W1 (unscaled); reused for hp'
__device__ __half g_hb[(size_t)NMAX * 128];  // h (unscaled, fp16)
__device__ __half g_zh[(size_t)NMAX * 64];   // z' = z*dinv (fp16)
__device__ float g_az[(size_t)NMAX * 64];    // aggregated z
__device__ int   g_cur[NMAX * CPAD];         // degree counters / fill cursors
__device__ int   g_bsrc[(size_t)NMAX * BCAP];// edge buckets (src ids)
__device__ __half g_w1h[128 * 128];          // W1 fp16
__device__ __half g_wdxh[64 * 128];          // Wdx fp16
__device__ __half g_wph[128 * 128];          // [Wmu|Wls] fp16 hi
__device__ __half g_wpl[128 * 128];          // [Wmu|Wls] fp16 lo (residual)
__device__ float g_bpack[128];               // [bmu | bls]

__device__ __forceinline__ float node_dinv(int node) {
    return rsqrtf(1.0f + (float)g_cur[node * CPAD]);
}

// ---------------- packed f32x2 helpers ---------------------------------------
__device__ __forceinline__ void addp2(unsigned long long& a, float lo, float hi) {
    unsigned long long t;
    asm("mov.b64 %0, {%1,%2};" : "=l"(t) : "f"(lo), "f"(hi));
    asm("add.rn.f32x2 %0, %0, %1;" : "+l"(a) : "l"(t));
}
__device__ __forceinline__ unsigned long long packf2(float lo, float hi) {
    unsigned long long t;
    asm("mov.b64 %0, {%1,%2};" : "=l"(t) : "f"(lo), "f"(hi));
    return t;
}
__device__ __forceinline__ float2 unpackf2(unsigned long long a) {
    float lo, hi;
    asm("mov.b64 {%0,%1}, %2;" : "=f"(lo), "=f"(hi) : "l"(a));
    return make_float2(lo, hi);
}
// a += w2 * q (packed fma)
__device__ __forceinline__ void fmap2(unsigned long long& a, unsigned long long w2,
                                      float lo, float hi) {
    unsigned long long t;
    asm("mov.b64 %0, {%1,%2};" : "=l"(t) : "f"(lo), "f"(hi));
    asm("fma.rn.f32x2 %0, %1, %2, %0;" : "+l"(a) : "l"(w2), "l"(t));
}
__device__ __forceinline__ void add_h4p(unsigned long long& a01, unsigned long long& a23,
                                        uint2 q) {
    float2 f0 = __half22float2(*reinterpret_cast<__half2*>(&q.x));
    float2 f1 = __half22float2(*reinterpret_cast<__half2*>(&q.y));
    addp2(a01, f0.x, f0.y);
    addp2(a23, f1.x, f1.y);
}
__device__ __forceinline__ void fma_h4p(unsigned long long& a01, unsigned long long& a23,
                                        uint2 q, unsigned long long w2) {
    float2 f0 = __half22float2(*reinterpret_cast<__half2*>(&q.x));
    float2 f1 = __half22float2(*reinterpret_cast<__half2*>(&q.y));
    fmap2(a01, w2, f0.x, f0.y);
    fmap2(a23, w2, f1.x, f1.y);
}
__device__ __forceinline__ void add_h2p(unsigned long long& a, unsigned q) {
    float2 f = __half22float2(*reinterpret_cast<__half2*>(&q));
    addp2(a, f.x, f.y);
}

// ---------------- weight conversion (independent branch) ---------------------
__global__ void cvt_weights(const float* __restrict__ W1, const float* __restrict__ Wdx,
                            const float* __restrict__ Wmu, const float* __restrict__ Wls,
                            const float* __restrict__ bmu, const float* __restrict__ bls)
{
    int i = blockIdx.x * blockDim.x + threadIdx.x;
    if (i < 128 * 128) g_w1h[i] = __float2half_rn(W1[i]);
    if (i < 64 * 128) g_wdxh[i] = __float2half_rn(Wdx[i]);
    if (i < 128 * 128) {
        int row = i >> 7, col = i & 127;
        float v = (col < 64) ? Wmu[row * 64 + col] : Wls[row * 64 + (col - 64)];
        __half h = __float2half_rn(v);
        g_wph[i] = h;
        g_wpl[i] = __float2half_rn(v - __half2float(h));
    }
    if (i < 64) { g_bpack[i] = bmu[i]; g_bpack[64 + i] = bls[i]; }
}

// ---------------- ONE-pass bucket fill ---------------------------------------
__global__ void bucket_fill(const int* __restrict__ src, const int* __restrict__ dst, int e) {
    int base = (blockIdx.x * blockDim.x + threadIdx.x) * 4;
    if (base + 4 <= e) {
        int4 s = *reinterpret_cast<const int4*>(src + base);
        int4 d = *reinterpret_cast<const int4*>(dst + base);
        int p0 = atomicAdd(&g_cur[d.x * CPAD], 1);
        int p1 = atomicAdd(&g_cur[d.y * CPAD], 1);
        int p2 = atomicAdd(&g_cur[d.z * CPAD], 1);
        int p3 = atomicAdd(&g_cur[d.w * CPAD], 1);
        if (p0 < BCAP) g_bsrc[(size_t)d.x * BCAP + p0] = s.x;
        if (p1 < BCAP) g_bsrc[(size_t)d.y * BCAP + p1] = s.y;
        if (p2 < BCAP) g_bsrc[(size_t)d.z * BCAP + p2] = s.z;
        if (p3 < BCAP) g_bsrc[(size_t)d.w * BCAP + p3] = s.w;
    } else {
        for (int i = base; i < e; i++) {
            int d = dst[i];
            int p = atomicAdd(&g_cur[d * CPAD], 1);
            if (p < BCAP) g_bsrc[(size_t)d * BCAP + p] = src[i];
        }
    }
}

// ---------------- agg_h: h = relu(dinv[d]*(Σ t[s]*dinv[s]) + b1) --------------
// t table is UNSCALED fp16; per-edge weight dinv[s] applied via packed FMA.
__global__ __launch_bounds__(256) void agg_h(
    const __half* __restrict__ feat, __half* __restrict__ outh,
    const float* __restrict__ bias, int n)
{
    int node = (blockIdx.x * blockDim.x + threadIdx.x) >> 5;
    if (node >= n) return;
    int lane = threadIdx.x & 31;
    const uint2* fb = reinterpret_cast<const uint2*>(feat);
    const int* bucket = g_bsrc + (size_t)node * BCAP;
    int raw = g_cur[node * CPAD];
    int cnt = min(raw, BCAP);
    float dv = rsqrtf(1.0f + (float)raw);

    unsigned long long a01 = 0ull, a23 = 0ull;
    // self term: weight dv (outer dv applied at the end => dv^2 total)
    fma_h4p(a01, a23, __ldg(fb + (size_t)node * 32 + lane), packf2(dv, dv));

    int j = 0;
    for (; j + 8 <= cnt; j += 8) {
        int4 s0 = *reinterpret_cast<const int4*>(bucket + j);
        int4 s1 = *reinterpret_cast<const int4*>(bucket + j + 4);
        float w0 = node_dinv(s0.x), w1 = node_dinv(s0.y);
        float w2 = node_dinv(s0.z), w3 = node_dinv(s0.w);
        float w4 = node_dinv(s1.x), w5 = node_dinv(s1.y);
        float w6 = node_dinv(s1.z), w7 = node_dinv(s1.w);
        uint2 q0 = __ldg(fb + (size_t)s0.x * 32 + lane);
        uint2 q1 = __ldg(fb + (size_t)s0.y * 32 + lane);
        uint2 q2 = __ldg(fb + (size_t)s0.z * 32 + lane);
        uint2 q3 = __ldg(fb + (size_t)s0.w * 32 + lane);
        uint2 q4 = __ldg(fb + (size_t)s1.x * 32 + lane);
        uint2 q5 = __ldg(fb + (size_t)s1.y * 32 + lane);
        uint2 q6 = __ldg(fb + (size_t)s1.z * 32 + lane);
        uint2 q7 = __ldg(fb + (size_t)s1.w * 32 + lane);
        fma_h4p(a01, a23, q0, packf2(w0, w0));
        fma_h4p(a01, a23, q1, packf2(w1, w1));
        fma_h4p(a01, a23, q2, packf2(w2, w2));
        fma_h4p(a01, a23, q3, packf2(w3, w3));
        fma_h4p(a01, a23, q4, packf2(w4, w4));
        fma_h4p(a01, a23, q5, packf2(w5, w5));
        fma_h4p(a01, a23, q6, packf2(w6, w6));
        fma_h4p(a01, a23, q7, packf2(w7, w7));
    }
    for (; j < cnt; j++) {
        int s = bucket[j];
        float w = node_dinv(s);
        fma_h4p(a01, a23, __ldg(fb + (size_t)s * 32 + lane), packf2(w, w));
    }

    float2 f01 = unpackf2(a01);
    float2 f23 = unpackf2(a23);
    float4 b = __ldg(reinterpret_cast<const float4*>(bias) + lane);
    float v0 = fmaxf(f01.x * dv + b.x, 0.f);
    float v1 = fmaxf(f01.y * dv + b.y, 0.f);
    float v2 = fmaxf(f23.x * dv + b.z, 0.f);
    float v3 = fmaxf(f23.y * dv + b.w, 0.f);
    __half2 h0 = __floats2half2_rn(v0, v1);
    __half2 h1 = __floats2half2_rn(v2, v3);
    uint2 q;
    q.x = *reinterpret_cast<unsigned*>(&h0);
    q.y = *reinterpret_cast<unsigned*>(&h1);
    *(reinterpret_cast<uint2*>(outh) + (size_t)node * 32 + lane) = q;
}

// ---------------- agg_z: unweighted gather of pre-scaled hp' table -----------
__device__ __forceinline__ void agg128_corep(const uint2* fb, int node, int lane, int cnt,
                                             unsigned long long& a01, unsigned long long& a23) {
    const int* bucket = g_bsrc + (size_t)node * BCAP;
    a01 = 0ull; a23 = 0ull;
    add_h4p(a01, a23, __ldg(fb + (size_t)node * 32 + lane));   // self (w folded)
    int j = 0;
    for (; j + 8 <= cnt; j += 8) {
        int4 s0 = *reinterpret_cast<const int4*>(bucket + j);
        int4 s1 = *reinterpret_cast<const int4*>(bucket + j + 4);
        uint2 q0 = __ldg(fb + (size_t)s0.x * 32 + lane);
        uint2 q1 = __ldg(fb + (size_t)s0.y * 32 + lane);
        uint2 q2 = __ldg(fb + (size_t)s0.z * 32 + lane);
        uint2 q3 = __ldg(fb + (size_t)s0.w * 32 + lane);
        uint2 q4 = __ldg(fb + (size_t)s1.x * 32 + lane);
        uint2 q5 = __ldg(fb + (size_t)s1.y * 32 + lane);
        uint2 q6 = __ldg(fb + (size_t)s1.z * 32 + lane);
        uint2 q7 = __ldg(fb + (size_t)s1.w * 32 + lane);
        add_h4p(a01, a23, q0); add_h4p(a01, a23, q1);
        add_h4p(a01, a23, q2); add_h4p(a01, a23, q3);
        add_h4p(a01, a23, q4); add_h4p(a01, a23, q5);
        add_h4p(a01, a23, q6); add_h4p(a01, a23, q7);
    }
    for (; j + 2 <= cnt; j += 2) {
        int s0 = bucket[j], s1 = bucket[j + 1];
        uint2 q0 = __ldg(fb + (size_t)s0 * 32 + lane);
        uint2 q1 = __ldg(fb + (size_t)s1 * 32 + lane);
        add_h4p(a01, a23, q0); add_h4p(a01, a23, q1);
    }
    for (; j < cnt; j++)
        add_h4p(a01, a23, __ldg(fb + (size_t)bucket[j] * 32 + lane));
}

// [mu|lv] = dinv*(sum hp') + bpack; z = eps*exp(0.5*lv)+mu; z' table = z*dinv
__global__ __launch_bounds__(256) void agg_z(
    const __half* __restrict__ feat, const float* __restrict__ eps,
    float* __restrict__ muO, float* __restrict__ lvO,
    float* __restrict__ zO, __half* __restrict__ zH, int n)
{
    int node = (blockIdx.x * blockDim.x + threadIdx.x) >> 5;
    if (node >= n) return;
    int lane = threadIdx.x & 31;
    int raw = g_cur[node * CPAD];
    int cnt = min(raw, BCAP);
    float dv = rsqrtf(1.0f + (float)raw);
    unsigned long long a01, a23;
    agg128_corep(reinterpret_cast<const uint2*>(feat), node, lane, cnt, a01, a23);
    float2 f01 = unpackf2(a01);
    float2 f23 = unpackf2(a23);
    float4 b = __ldg(reinterpret_cast<const float4*>(g_bpack) + lane);
    float4 acc;
    acc.x = f01.x * dv + b.x;
    acc.y = f01.y * dv + b.y;
    acc.z = f23.x * dv + b.z;
    acc.w = f23.y * dv + b.w;

    float4 other;   // lv cols for lanes<16
    other.x = __shfl_xor_sync(0xffffffffu, acc.x, 16);
    other.y = __shfl_xor_sync(0xffffffffu, acc.y, 16);
    other.z = __shfl_xor_sync(0xffffffffu, acc.z, 16);
    other.w = __shfl_xor_sync(0xffffffffu, acc.w, 16);

    if (lane < 16) {
        float4 ep = __ldg(reinterpret_cast<const float4*>(eps + (size_t)node * 64) + lane);
        float4 zv;
        zv.x = ep.x * expf(0.5f * other.x) + acc.x;
        zv.y = ep.y * expf(0.5f * other.y) + acc.y;
        zv.z = ep.z * expf(0.5f * other.z) + acc.z;
        zv.w = ep.w * expf(0.5f * other.w) + acc.w;
        *(reinterpret_cast<float4*>(muO + (size_t)node * 64) + lane) = acc;
        *(reinterpret_cast<float4*>(zO + (size_t)node * 64) + lane) = zv;
        __half2 h0 = __floats2half2_rn(zv.x * dv, zv.y * dv);
        __half2 h1 = __floats2half2_rn(zv.z * dv, zv.w * dv);
        uint2 q;
        q.x = *reinterpret_cast<unsigned*>(&h0);
        q.y = *reinterpret_cast<unsigned*>(&h1);
        *(reinterpret_cast<uint2*>(zH) + (size_t)node * 16 + lane) = q;
    } else {
        *(reinterpret_cast<float4*>(lvO + (size_t)node * 64) + (lane - 16)) = acc;
    }
}

// ---------------- az agg (64-wide) + FUSED heads epilogue --------------------
__global__ __launch_bounds__(256) void agg64_heads(
    const __half* __restrict__ feat, const float* __restrict__ z,
    const float* __restrict__ u,
    const float* __restrict__ Wg, const float* __restrict__ bg,
    const float* __restrict__ Wlc, const float* __restrict__ blc,
    float* __restrict__ azO, float* __restrict__ gender,
    float* __restrict__ label, int n)
{
    int node = (blockIdx.x * blockDim.x + threadIdx.x) >> 5;
    if (node >= n) return;
    int lane = threadIdx.x & 31;
    const unsigned* fb = reinterpret_cast<const unsigned*>(feat);
    const int* bucket = g_bsrc + (size_t)node * BCAP;
    int raw = g_cur[node * CPAD];
    int cnt = min(raw, BCAP);
    float dv = rsqrtf(1.0f + (float)raw);

    unsigned long long a = 0ull;
    add_h2p(a, __ldg(fb + (size_t)node * 32 + lane));
    int j = 0;
    for (; j + 8 <= cnt; j += 8) {
        int4 s0 = *reinterpret_cast<const int4*>(bucket + j);
        int4 s1 = *reinterpret_cast<const int4*>(bucket + j + 4);
        unsigned q0 = __ldg(fb + (size_t)s0.x * 32 + lane);
        unsigned q1 = __ldg(fb + (size_t)s0.y * 32 + lane);
        unsigned q2 = __ldg(fb + (size_t)s0.z * 32 + lane);
        unsigned q3 = __ldg(fb + (size_t)s0.w * 32 + lane);
        unsigned q4 = __ldg(fb + (size_t)s1.x * 32 + lane);
        unsigned q5 = __ldg(fb + (size_t)s1.y * 32 + lane);
        unsigned q6 = __ldg(fb + (size_t)s1.z * 32 + lane);
        unsigned q7 = __ldg(fb + (size_t)s1.w * 32 + lane);
        add_h2p(a, q0); add_h2p(a, q1); add_h2p(a, q2); add_h2p(a, q3);
        add_h2p(a, q4); add_h2p(a, q5); add_h2p(a, q6); add_h2p(a, q7);
    }
    for (; j < cnt; j++)
        add_h2p(a, __ldg(fb + (size_t)bucket[j] * 32 + lane));

    float2 az = unpackf2(a);
    az.x *= dv; az.y *= dv;
    *(reinterpret_cast<float2*>(azO + (size_t)node * 64) + lane) = az;

    // ---- fused heads: lane k holds az dims (2k, 2k+1) ----
    float2 zz = __ldg(reinterpret_cast<const float2*>(z + (size_t)node * 64) + lane);
    int k = lane * 2;
    float p0 = az.x * Wg[k * 2 + 0] + az.y * Wg[(k + 1) * 2 + 0];
    float p1 = az.x * Wg[k * 2 + 1] + az.y * Wg[(k + 1) * 2 + 1];
    float pl = zz.x * Wlc[k] + zz.y * Wlc[k + 1];
#pragma unroll
    for (int off = 16; off; off >>= 1) {
        p0 += __shfl_xor_sync(0xffffffffu, p0, off);
        p1 += __shfl_xor_sync(0xffffffffu, p1, off);
        pl += __shfl_xor_sync(0xffffffffu, pl, off);
    }
    if (lane == 0) {
        float l0 = p0 + bg[0], l1 = p1 + bg[1];
        float u0 = u[(size_t)node * 2], u1 = u[(size_t)node * 2 + 1];
        float gn0 = -logf(-logf(u0 + 1e-20f) + 1e-20f);
        float gn1 = -logf(-logf(u1 + 1e-20f) + 1e-20f);
        float a0 = l0 + gn0, a1 = l1 + gn1;
        float m = fmaxf(a0, a1);
        float e0 = expf(a0 - m), e1 = expf(a1 - m);
        float inv = 1.0f / (e0 + e1);
        float s0 = e0 * inv, s1 = e1 * inv;
        float h0 = (s0 >= s1) ? 1.0f : 0.0f;
        float h1 = 1.0f - h0;
        gender[(size_t)node * 2 + 0] = (h0 - s0) + s0;
        gender[(size_t)node * 2 + 1] = (h1 - s1) + s1;
        label[node] = pl + blc[0];
    }
}

// ---------------- HMMA helpers ------------------------------------------------
__device__ __forceinline__ void ldsm4(unsigned& r0, unsigned& r1, unsigned& r2,
                                      unsigned& r3, unsigned addr) {
    asm volatile("ldmatrix.sync.aligned.m8n8.x4.shared.b16 {%0,%1,%2,%3}, [%4];"
                 : "=r"(r0), "=r"(r1), "=r"(r2), "=r"(r3) : "r"(addr));
}
__device__ __forceinline__ void ldsm4t(unsigned& r0, unsigned& r1, unsigned& r2,
                                       unsigned& r3, unsigned addr) {
    asm volatile("ldmatrix.sync.aligned.m8n8.x4.trans.shared.b16 {%0,%1,%2,%3}, [%4];"
                 : "=r"(r0), "=r"(r1), "=r"(r2), "=r"(r3) : "r"(addr));
}
__device__ __forceinline__ void mma16816(float* d, const unsigned* a, const unsigned* b) {
    asm volatile("mma.sync.aligned.m16n8k16.row.col.f32.f16.f16.f32 "
                 "{%0,%1,%2,%3}, {%4,%5,%6,%7}, {%8,%9}, {%0,%1,%2,%3};"
                 : "+f"(d[0]), "+f"(d[1]), "+f"(d[2]), "+f"(d[3])
                 : "r"(a[0]), "r"(a[1]), "r"(a[2]), "r"(a[3]), "r"(b[0]), "r"(b[1]));
}

// ---------------- HMMA GEMM: A fp32 @ B fp16; fp32 C and/or fp16 Ch ----------
__global__ __launch_bounds__(256) void hgemm128(
    const float* __restrict__ A, const __half* __restrict__ Bh,
    const float* __restrict__ bias, float* __restrict__ C,
    __half* __restrict__ Ch, int N, int K)
{
    __shared__ __half sAh[128][24];
    __shared__ __half sBh[16][136];

    int tid = threadIdx.x;
    int lane = tid & 31;
    int wid = tid >> 5;
    int wm = (wid & 3) * 32;
    int wn = (wid >> 2) * 64;
    int row0 = blockIdx.y * 128;

    float acc[2][8][4];
#pragma unroll
    for (int i = 0; i < 2; i++)
#pragma unroll
        for (int j = 0; j < 8; j++)
#pragma unroll
            for (int k = 0; k < 4; k++) acc[i][j][k] = 0.f;

    int ar = tid >> 1, ak = (tid & 1) * 8;
    int br = tid & 15, bc = (tid >> 4) * 8;

    unsigned sa_base = (unsigned)__cvta_generic_to_shared(&sAh[0][0]);
    unsigned sb_base = (unsigned)__cvta_generic_to_shared(&sBh[0][0]);

    const int KSTEPS = K >> 4;
    for (int ks = 0; ks < KSTEPS; ks++) {
        int k0 = ks << 4;
        float va[8] = {0, 0, 0, 0, 0, 0, 0, 0};
        if (row0 + ar < N) {
            const float* ap = A + (size_t)(row0 + ar) * K + k0 + ak;
            float4 f0 = *reinterpret_cast<const float4*>(ap);
            float4 f1 = *reinterpret_cast<const float4*>(ap + 4);
            va[0] = f0.x; va[1] = f0.y; va[2] = f0.z; va[3] = f0.w;
            va[4] = f1.x; va[5] = f1.y; va[6] = f1.z; va[7] = f1.w;
        }
        __half hh[8];
#pragma unroll
        for (int i = 0; i < 8; i++) hh[i] = __float2half_rn(va[i]);
        *reinterpret_cast<uint4*>(&sAh[ar][ak]) = *reinterpret_cast<uint4*>(hh);
        *reinterpret_cast<uint4*>(&sBh[br][bc]) =
            *reinterpret_cast<const uint4*>(Bh + (size_t)(k0 + br) * 128 + bc);
        __syncthreads();

        unsigned afh[2][4];
        int fr = lane & 15;
        int fc = (lane >> 4) * 8;
#pragma unroll
        for (int am = 0; am < 2; am++) {
            unsigned off = (unsigned)(((wm + am * 16 + fr) * 24 + fc) << 1);
            ldsm4(afh[am][0], afh[am][1], afh[am][2], afh[am][3], sa_base + off);
        }
        unsigned bfh[8][2];
#pragma unroll
        for (int bn = 0; bn < 4; bn++) {
            unsigned off = (unsigned)((fr * 136 + wn + bn * 16 + fc) << 1);
            ldsm4t(bfh[bn * 2][0], bfh[bn * 2][1], bfh[bn * 2 + 1][0], bfh[bn * 2 + 1][1],
                   sb_base + off);
        }
#pragma unroll
        for (int am = 0; am < 2; am++)
#pragma unroll
            for (int an = 0; an < 8; an++)
                mma16816(acc[am][an], afh[am], bfh[an]);
        __syncthreads();
    }

#pragma unroll
    for (int am = 0; am < 2; am++) {
        int rr = row0 + wm + am * 16 + (lane >> 2);
#pragma unroll
        for (int an = 0; an < 8; an++) {
            int cc = wn + an * 8 + (lane & 3) * 2;
            float bv0 = bias ? __ldg(bias + cc) : 0.f;
            float bv1 = bias ? __ldg(bias + cc + 1) : 0.f;
            if (rr < N) {
                float v0 = acc[am][an][0] + bv0, v1 = acc[am][an][1] + bv1;
                if (C) *reinterpret_cast<float2*>(C + (size_t)rr * 128 + cc) = make_float2(v0, v1);
                if (Ch) *reinterpret_cast<__half2*>(Ch + (size_t)rr * 128 + cc) = __floats2half2_rn(v0, v1);
            }
            if (rr + 8 < N) {
                float v2 = acc[am][an][2] + bv0, v3 = acc[am][an][3] + bv1;
                if (C) *reinterpret_cast<float2*>(C + (size_t)(rr + 8) * 128 + cc) = make_float2(v2, v3);
                if (Ch) *reinterpret_cast<__half2*>(Ch + (size_t)(rr + 8) * 128 + cc) = __floats2half2_rn(v2, v3);
            }
        }
    }
}

// ---------------- HMMA GEMM: hp' = (h @ [Wmu|Wls]) * dinv[row] ---------------
__global__ __launch_bounds__(256) void hgemm_hh(
    const __half* __restrict__ A, const __half* __restrict__ Bh,
    const __half* __restrict__ Bl, __half* __restrict__ Chp, int N)
{
    const int K = 128;
    __shared__ __half sAh[128][24];
    __shared__ __half sBh[16][136];
    __shared__ __half sBl[16][136];

    int tid = threadIdx.x;
    int lane = tid & 31;
    int wid = tid >> 5;
    int wm = (wid & 3) * 32;
    int wn = (wid >> 2) * 64;
    int row0 = blockIdx.y * 128;

    float acc[2][8][4];
#pragma unroll
    for (int i = 0; i < 2; i++)
#pragma unroll
        for (int j = 0; j < 8; j++)
#pragma unroll
            for (int k = 0; k < 4; k++) acc[i][j][k] = 0.f;

    int ar = tid >> 1, ak = (tid & 1) * 8;
    int br = tid & 15, bc = (tid >> 4) * 8;

    unsigned sa_base = (unsigned)__cvta_generic_to_shared(&sAh[0][0]);
    unsigned sb_base = (unsigned)__cvta_generic_to_shared(&sBh[0][0]);
    unsigned sbl_base = (unsigned)__cvta_generic_to_shared(&sBl[0][0]);

    for (int ks = 0; ks < 8; ks++) {
        int k0 = ks << 4;
        uint4 av = make_uint4(0, 0, 0, 0);
        if (row0 + ar < N)
            av = *reinterpret_cast<const uint4*>(A + (size_t)(row0 + ar) * K + k0 + ak);
        *reinterpret_cast<uint4*>(&sAh[ar][ak]) = av;
        *reinterpret_cast<uint4*>(&sBh[br][bc]) =
            *reinterpret_cast<const uint4*>(Bh + (size_t)(k0 + br) * 128 + bc);
        *reinterpret_cast<uint4*>(&sBl[br][bc]) =
            *reinterpret_cast<const uint4*>(Bl + (size_t)(k0 + br) * 128 + bc);
        __syncthreads();

        unsigned afh[2][4];
        int fr = lane & 15;
        int fc = (lane >> 4) * 8;
#pragma unroll
        for (int am = 0; am < 2; am++) {
            unsigned off = (unsigned)(((wm + am * 16 + fr) * 24 + fc) << 1);
            ldsm4(afh[am][0], afh[am][1], afh[am][2], afh[am][3], sa_base + off);
        }
        unsigned bfh[8][2], bfl[8][2];
#pragma unroll
        for (int bn = 0; bn < 4; bn++) {
            unsigned off = (unsigned)((fr * 136 + wn + bn * 16 + fc) << 1);
            ldsm4t(bfh[bn * 2][0], bfh[bn * 2][1], bfh[bn * 2 + 1][0], bfh[bn * 2 + 1][1],
                   sb_base + off);
            ldsm4t(bfl[bn * 2][0], bfl[bn * 2][1], bfl[bn * 2 + 1][0], bfl[bn * 2 + 1][1],
                   sbl_base + off);
        }
#pragma unroll
        for (int am = 0; am < 2; am++)
#pragma unroll
            for (int an = 0; an < 8; an++) {
                mma16816(acc[am][an], afh[am], bfh[an]);
                mma16816(acc[am][an], afh[am], bfl[an]);
            }
        __syncthreads();
    }

#pragma unroll
    for (int am = 0; am < 2; am++) {
        int rr = row0 + wm + am * 16 + (lane >> 2);
        float s0 = (rr < N) ? node_dinv(rr) : 1.f;
        float s1 = (rr + 8 < N) ? node_dinv(rr + 8) : 1.f;
#pragma unroll
        for (int an = 0; an < 8; an++) {
            int cc = wn + an * 8 + (lane & 3) * 2;
            if (rr < N)
                *reinterpret_cast<__half2*>(Chp + (size_t)rr * 128 + cc) =
                    __floats2half2_rn(acc[am][an][0] * s0, acc[am][an][1] * s0);
            if (rr + 8 < N)
                *reinterpret_cast<__half2*>(Chp + (size_t)(rr + 8) * 128 + cc) =
                    __floats2half2_rn(acc[am][an][2] * s1, acc[am][an][3] * s1);
        }
    }
}

// ---------------- launch -----------------------------------------------------
extern "C" void kernel_launch(void* const* d_in, const int* in_sizes, int n_in,
                              void* d_out, int out_size) {
    const float* x   = (const float*)d_in[0];
    const int*   ei  = (const int*)d_in[1];
    const float* eps = (const float*)d_in[2];
    const float* u   = (const float*)d_in[3];
    const float* W1  = (const float*)d_in[4];
    const float* b1  = (const float*)d_in[5];
    const float* Wmu = (const float*)d_in[6];
    const float* bmu = (const float*)d_in[7];
    const float* Wls = (const float*)d_in[8];
    const float* bls = (const float*)d_in[9];
    const float* Wdx = (const float*)d_in[10];
    const float* bdx = (const float*)d_in[11];
    const float* Wg  = (const float*)d_in[12];
    const float* bg  = (const float*)d_in[13];
    const float* Wlc = (const float*)d_in[14];
    const float* blc = (const float*)d_in[15];

    const int N = in_sizes[0] / 128;
    const int E = in_sizes[1] / 2;
    const int* src = ei;
    const int* dst = ei + E;

    float* out    = (float*)d_out;
    float* recon  = out;                     // [N,128]
    float* gender = out + (size_t)N * 128;   // [N,2]
    float* label  = gender + (size_t)N * 2;  // [N,1]
    float* mu     = label + N;               // [N,64]
    float* lv     = mu + (size_t)N * 64;     // [N,64]
    float* z      = lv + (size_t)N * 64;     // [N,64]

    float *p_az;
    __half *p_tb, *p_hb, *p_zh, *p_w1h, *p_wdxh, *p_wph, *p_wpl;
    int *p_cur;
    cudaGetSymbolAddress((void**)&p_tb, g_tb);
    cudaGetSymbolAddress((void**)&p_hb, g_hb);
    cudaGetSymbolAddress((void**)&p_zh, g_zh);
    cudaGetSymbolAddress((void**)&p_az, g_az);
    cudaGetSymbolAddress((void**)&p_w1h, g_w1h);
    cudaGetSymbolAddress((void**)&p_wdxh, g_wdxh);
    cudaGetSymbolAddress((void**)&p_wph, g_wph);
    cudaGetSymbolAddress((void**)&p_wpl, g_wpl);
    cudaGetSymbolAddress((void**)&p_cur, g_cur);

    // persistent side stream / events for graph-parallel branch
    static cudaStream_t s1 = nullptr;
    static cudaEvent_t evRoot = nullptr, evW = nullptr;
    if (!s1) {
        cudaStreamCreateWithFlags(&s1, cudaStreamNonBlocking);
        cudaEventCreateWithFlags(&evRoot, cudaEventDisableTiming);
        cudaEventCreateWithFlags(&evW, cudaEventDisableTiming);
    }

    const int T = 256;
    int nodeWarpBlocks = (int)(((size_t)N * 32 + T - 1) / T);
    int e4Blocks = ((E + 3) / 4 + T - 1) / T;
    dim3 gg(1, (N + 127) / 128);

    // ---- fork: weights + unscaled t-GEMM parallel to bucket fill ----
    cudaEventRecord(evRoot, 0);
    cudaStreamWaitEvent(s1, evRoot, 0);
    cvt_weights<<<(128 * 128 + T - 1) / T, T, 0, s1>>>(W1, Wdx, Wmu, Wls, bmu, bls);
    hgemm128<<<gg, 256, 0, s1>>>(x, p_w1h, nullptr, nullptr, p_tb, N, 128);
    cudaEventRecord(evW, s1);

    // ---- main stream: one-pass bucket CSR ----
    cudaMemsetAsync(p_cur, 0, (size_t)N * CPAD * sizeof(int), 0);
    bucket_fill<<<e4Blocks, T>>>(src, dst, E);

    // ---- join; h = relu(dinv[d] * Σ t[s]*dinv[s] + b1)  (per-edge weights) ----
    cudaStreamWaitEvent(0, evW, 0);
    agg_h<<<nodeWarpBlocks, T>>>(p_tb, p_hb, b1, N);

    // hp' = (h @ [Wmu|Wls]) * dinv  (fp16 table, reuses g_tb)
    hgemm_hh<<<gg, 256>>>(p_hb, p_wph, p_wpl, p_tb, N);

    // [mu|lv] = dinv * (A-sum of hp') + b; z; z' table
    agg_z<<<nodeWarpBlocks, T>>>(p_tb, eps, mu, lv, z, p_zh, N);

    // az = dinv * (A-sum of z'); fused gender/label heads
    agg64_heads<<<nodeWarpBlocks, T>>>(p_zh, z, u, Wg, bg, Wlc, blc,
                                       p_az, gender, label, N);

    // recon_x = az @ Wdx + bdx
    hgemm128<<<gg, 256>>>(p_az, p_wdxh, bdx, recon, nullptr, N, 64);
}

// round 14
// speedup vs baseline: 1.1538x; 1.1538x over previous
#include <cuda_runtime.h>
#include <cuda_fp16.h>
#include <math.h>

#define NMAX 50048
#define EMAX 1700000
#define CPAD 8     // cursor padding: 1 int per 32B sector
#define BCAP 128   // bucket capacity per node (deg ~ Poisson(32); 17 sigma)

// ---------------- scratch (device globals) ----------------------------------
__device__ __half g_tb[(size_t)NMAX * 128];  // t' = (x@W1)*dinv; reused for hp'
__device__ __half g_hb[(size_t)NMAX * 128];  // h (unscaled, fp16)
__device__ __half g_zh[(size_t)NMAX * 64];   // z' = z*dinv (fp16)
__device__ float g_az[(size_t)NMAX * 64];    // aggregated z
__device__ int   g_cur[NMAX * CPAD];         // degree counters / fill cursors
__device__ int   g_bsrc[(size_t)NMAX * BCAP];// edge buckets (src ids)
__device__ __half g_w1h[128 * 128];          // W1 fp16
__device__ __half g_wdxh[64 * 128];          // Wdx fp16
__device__ __half g_wph[128 * 128];          // [Wmu|Wls] fp16
__device__ float g_bpack[128];               // [bmu | bls]

__device__ __forceinline__ float node_dinv(int node) {
    return rsqrtf(1.0f + (float)g_cur[node * CPAD]);
}

// ---------------- packed f32x2 helpers ---------------------------------------
__device__ __forceinline__ void addp2(unsigned long long& a, float lo, float hi) {
    unsigned long long t;
    asm("mov.b64 %0, {%1,%2};" : "=l"(t) : "f"(lo), "f"(hi));
    asm("add.rn.f32x2 %0, %0, %1;" : "+l"(a) : "l"(t));
}
__device__ __forceinline__ float2 unpackf2(unsigned long long a) {
    float lo, hi;
    asm("mov.b64 {%0,%1}, %2;" : "=f"(lo), "=f"(hi) : "l"(a));
    return make_float2(lo, hi);
}
__device__ __forceinline__ void add_h4p(unsigned long long& a01, unsigned long long& a23,
                                        uint2 q) {
    float2 f0 = __half22float2(*reinterpret_cast<__half2*>(&q.x));
    float2 f1 = __half22float2(*reinterpret_cast<__half2*>(&q.y));
    addp2(a01, f0.x, f0.y);
    addp2(a23, f1.x, f1.y);
}
__device__ __forceinline__ void add_h2p(unsigned long long& a, unsigned q) {
    float2 f = __half22float2(*reinterpret_cast<__half2*>(&q));
    addp2(a, f.x, f.y);
}

// ---------------- weight conversion (independent branch) ---------------------
__global__ void cvt_weights(const float* __restrict__ W1, const float* __restrict__ Wdx,
                            const float* __restrict__ Wmu, const float* __restrict__ Wls,
                            const float* __restrict__ bmu, const float* __restrict__ bls)
{
    int i = blockIdx.x * blockDim.x + threadIdx.x;
    if (i < 128 * 128) g_w1h[i] = __float2half_rn(W1[i]);
    if (i < 64 * 128) g_wdxh[i] = __float2half_rn(Wdx[i]);
    if (i < 128 * 128) {
        int row = i >> 7, col = i & 127;
        float v = (col < 64) ? Wmu[row * 64 + col] : Wls[row * 64 + (col - 64)];
        g_wph[i] = __float2half_rn(v);
    }
    if (i < 64) { g_bpack[i] = bmu[i]; g_bpack[64 + i] = bls[i]; }
}

// ---------------- ONE-pass bucket fill ---------------------------------------
__global__ void bucket_fill(const int* __restrict__ src, const int* __restrict__ dst, int e) {
    int base = (blockIdx.x * blockDim.x + threadIdx.x) * 4;
    if (base + 4 <= e) {
        int4 s = *reinterpret_cast<const int4*>(src + base);
        int4 d = *reinterpret_cast<const int4*>(dst + base);
        int p0 = atomicAdd(&g_cur[d.x * CPAD], 1);
        int p1 = atomicAdd(&g_cur[d.y * CPAD], 1);
        int p2 = atomicAdd(&g_cur[d.z * CPAD], 1);
        int p3 = atomicAdd(&g_cur[d.w * CPAD], 1);
        if (p0 < BCAP) g_bsrc[(size_t)d.x * BCAP + p0] = s.x;
        if (p1 < BCAP) g_bsrc[(size_t)d.y * BCAP + p1] = s.y;
        if (p2 < BCAP) g_bsrc[(size_t)d.z * BCAP + p2] = s.z;
        if (p3 < BCAP) g_bsrc[(size_t)d.w * BCAP + p3] = s.w;
    } else {
        for (int i = base; i < e; i++) {
            int d = dst[i];
            int p = atomicAdd(&g_cur[d * CPAD], 1);
            if (p < BCAP) g_bsrc[(size_t)d * BCAP + p] = src[i];
        }
    }
}

// ---------------- t' = t * dinv (in place, fp16) ------------------------------
__global__ void scale_t(__half* __restrict__ tb, int n) {
    int i = blockIdx.x * blockDim.x + threadIdx.x;  // one uint4 = 8 halves
    int total = n * 16;
    if (i >= total) return;
    float dv = node_dinv(i >> 4);
    uint4 q = reinterpret_cast<uint4*>(tb)[i];
    unsigned* w = reinterpret_cast<unsigned*>(&q);
#pragma unroll
    for (int k = 0; k < 4; k++) {
        float2 f = __half22float2(*reinterpret_cast<__half2*>(&w[k]));
        __half2 h = __floats2half2_rn(f.x * dv, f.y * dv);
        w[k] = *reinterpret_cast<unsigned*>(&h);
    }
    reinterpret_cast<uint4*>(tb)[i] = q;
}

// ---------------- agg core: warp per node, 128-wide, packed ------------------
__device__ __forceinline__ void agg128_corep(const uint2* fb, int node, int lane, int cnt,
                                             unsigned long long& a01, unsigned long long& a23) {
    const int* bucket = g_bsrc + (size_t)node * BCAP;
    a01 = 0ull; a23 = 0ull;
    add_h4p(a01, a23, __ldg(fb + (size_t)node * 32 + lane));   // self (w folded)
    int j = 0;
    for (; j + 8 <= cnt; j += 8) {
        int4 s0 = *reinterpret_cast<const int4*>(bucket + j);
        int4 s1 = *reinterpret_cast<const int4*>(bucket + j + 4);
        uint2 q0 = __ldg(fb + (size_t)s0.x * 32 + lane);
        uint2 q1 = __ldg(fb + (size_t)s0.y * 32 + lane);
        uint2 q2 = __ldg(fb + (size_t)s0.z * 32 + lane);
        uint2 q3 = __ldg(fb + (size_t)s0.w * 32 + lane);
        uint2 q4 = __ldg(fb + (size_t)s1.x * 32 + lane);
        uint2 q5 = __ldg(fb + (size_t)s1.y * 32 + lane);
        uint2 q6 = __ldg(fb + (size_t)s1.z * 32 + lane);
        uint2 q7 = __ldg(fb + (size_t)s1.w * 32 + lane);
        add_h4p(a01, a23, q0); add_h4p(a01, a23, q1);
        add_h4p(a01, a23, q2); add_h4p(a01, a23, q3);
        add_h4p(a01, a23, q4); add_h4p(a01, a23, q5);
        add_h4p(a01, a23, q6); add_h4p(a01, a23, q7);
    }
    for (; j + 2 <= cnt; j += 2) {
        int s0 = bucket[j], s1 = bucket[j + 1];
        uint2 q0 = __ldg(fb + (size_t)s0 * 32 + lane);
        uint2 q1 = __ldg(fb + (size_t)s1 * 32 + lane);
        add_h4p(a01, a23, q0); add_h4p(a01, a23, q1);
    }
    for (; j < cnt; j++)
        add_h4p(a01, a23, __ldg(fb + (size_t)bucket[j] * 32 + lane));
}

// h = relu(dinv*(sum) + b1) -> fp16 table
__global__ __launch_bounds__(256) void agg_h(
    const __half* __restrict__ feat, __half* __restrict__ outh,
    const float* __restrict__ bias, int n)
{
    int node = (blockIdx.x * blockDim.x + threadIdx.x) >> 5;
    if (node >= n) return;
    int lane = threadIdx.x & 31;
    int raw = g_cur[node * CPAD];
    int cnt = min(raw, BCAP);
    float dv = rsqrtf(1.0f + (float)raw);
    unsigned long long a01, a23;
    agg128_corep(reinterpret_cast<const uint2*>(feat), node, lane, cnt, a01, a23);
    float2 f01 = unpackf2(a01);
    float2 f23 = unpackf2(a23);
    float4 b = __ldg(reinterpret_cast<const float4*>(bias) + lane);
    float v0 = fmaxf(f01.x * dv + b.x, 0.f);
    float v1 = fmaxf(f01.y * dv + b.y, 0.f);
    float v2 = fmaxf(f23.x * dv + b.z, 0.f);
    float v3 = fmaxf(f23.y * dv + b.w, 0.f);
    __half2 h0 = __floats2half2_rn(v0, v1);
    __half2 h1 = __floats2half2_rn(v2, v3);
    uint2 q;
    q.x = *reinterpret_cast<unsigned*>(&h0);
    q.y = *reinterpret_cast<unsigned*>(&h1);
    *(reinterpret_cast<uint2*>(outh) + (size_t)node * 32 + lane) = q;
}

// [mu|lv] = dinv*(sum hp') + bpack; z = eps*exp(0.5*lv)+mu; z' table = z*dinv
__global__ __launch_bounds__(256) void agg_z(
    const __half* __restrict__ feat, const float* __restrict__ eps,
    float* __restrict__ muO, float* __restrict__ lvO,
    float* __restrict__ zO, __half* __restrict__ zH, int n)
{
    int node = (blockIdx.x * blockDim.x + threadIdx.x) >> 5;
    if (node >= n) return;
    int lane = threadIdx.x & 31;
    int raw = g_cur[node * CPAD];
    int cnt = min(raw, BCAP);
    float dv = rsqrtf(1.0f + (float)raw);
    unsigned long long a01, a23;
    agg128_corep(reinterpret_cast<const uint2*>(feat), node, lane, cnt, a01, a23);
    float2 f01 = unpackf2(a01);
    float2 f23 = unpackf2(a23);
    float4 b = __ldg(reinterpret_cast<const float4*>(g_bpack) + lane);
    float4 acc;
    acc.x = f01.x * dv + b.x;
    acc.y = f01.y * dv + b.y;
    acc.z = f23.x * dv + b.z;
    acc.w = f23.y * dv + b.w;

    float4 other;   // lv cols for lanes<16
    other.x = __shfl_xor_sync(0xffffffffu, acc.x, 16);
    other.y = __shfl_xor_sync(0xffffffffu, acc.y, 16);
    other.z = __shfl_xor_sync(0xffffffffu, acc.z, 16);
    other.w = __shfl_xor_sync(0xffffffffu, acc.w, 16);

    if (lane < 16) {
        float4 ep = __ldg(reinterpret_cast<const float4*>(eps + (size_t)node * 64) + lane);
        float4 zv;
        zv.x = ep.x * expf(0.5f * other.x) + acc.x;
        zv.y = ep.y * expf(0.5f * other.y) + acc.y;
        zv.z = ep.z * expf(0.5f * other.z) + acc.z;
        zv.w = ep.w * expf(0.5f * other.w) + acc.w;
        *(reinterpret_cast<float4*>(muO + (size_t)node * 64) + lane) = acc;
        *(reinterpret_cast<float4*>(zO + (size_t)node * 64) + lane) = zv;
        __half2 h0 = __floats2half2_rn(zv.x * dv, zv.y * dv);
        __half2 h1 = __floats2half2_rn(zv.z * dv, zv.w * dv);
        uint2 q;
        q.x = *reinterpret_cast<unsigned*>(&h0);
        q.y = *reinterpret_cast<unsigned*>(&h1);
        *(reinterpret_cast<uint2*>(zH) + (size_t)node * 16 + lane) = q;
    } else {
        *(reinterpret_cast<float4*>(lvO + (size_t)node * 64) + (lane - 16)) = acc;
    }
}

// ---------------- az agg (64-wide) + FUSED heads epilogue --------------------
__global__ __launch_bounds__(256) void agg64_heads(
    const __half* __restrict__ feat, const float* __restrict__ z,
    const float* __restrict__ u,
    const float* __restrict__ Wg, const float* __restrict__ bg,
    const float* __restrict__ Wlc, const float* __restrict__ blc,
    float* __restrict__ azO, float* __restrict__ gender,
    float* __restrict__ label, int n)
{
    int node = (blockIdx.x * blockDim.x + threadIdx.x) >> 5;
    if (node >= n) return;
    int lane = threadIdx.x & 31;
    const unsigned* fb = reinterpret_cast<const unsigned*>(feat);
    const int* bucket = g_bsrc + (size_t)node * BCAP;
    int raw = g_cur[node * CPAD];
    int cnt = min(raw, BCAP);
    float dv = rsqrtf(1.0f + (float)raw);

    unsigned long long a = 0ull;
    add_h2p(a, __ldg(fb + (size_t)node * 32 + lane));
    int j = 0;
    for (; j + 8 <= cnt; j += 8) {
        int4 s0 = *reinterpret_cast<const int4*>(bucket + j);
        int4 s1 = *reinterpret_cast<const int4*>(bucket + j + 4);
        unsigned q0 = __ldg(fb + (size_t)s0.x * 32 + lane);
        unsigned q1 = __ldg(fb + (size_t)s0.y * 32 + lane);
        unsigned q2 = __ldg(fb + (size_t)s0.z * 32 + lane);
        unsigned q3 = __ldg(fb + (size_t)s0.w * 32 + lane);
        unsigned q4 = __ldg(fb + (size_t)s1.x * 32 + lane);
        unsigned q5 = __ldg(fb + (size_t)s1.y * 32 + lane);
        unsigned q6 = __ldg(fb + (size_t)s1.z * 32 + lane);
        unsigned q7 = __ldg(fb + (size_t)s1.w * 32 + lane);
        add_h2p(a, q0); add_h2p(a, q1); add_h2p(a, q2); add_h2p(a, q3);
        add_h2p(a, q4); add_h2p(a, q5); add_h2p(a, q6); add_h2p(a, q7);
    }
    for (; j < cnt; j++)
        add_h2p(a, __ldg(fb + (size_t)bucket[j] * 32 + lane));

    float2 az = unpackf2(a);
    az.x *= dv; az.y *= dv;
    *(reinterpret_cast<float2*>(azO + (size_t)node * 64) + lane) = az;

    // ---- fused heads: lane k holds az dims (2k, 2k+1) ----
    float2 zz = __ldg(reinterpret_cast<const float2*>(z + (size_t)node * 64) + lane);
    int k = lane * 2;
    float p0 = az.x * Wg[k * 2 + 0] + az.y * Wg[(k + 1) * 2 + 0];
    float p1 = az.x * Wg[k * 2 + 1] + az.y * Wg[(k + 1) * 2 + 1];
    float pl = zz.x * Wlc[k] + zz.y * Wlc[k + 1];
#pragma unroll
    for (int off = 16; off; off >>= 1) {
        p0 += __shfl_xor_sync(0xffffffffu, p0, off);
        p1 += __shfl_xor_sync(0xffffffffu, p1, off);
        pl += __shfl_xor_sync(0xffffffffu, pl, off);
    }
    if (lane == 0) {
        float l0 = p0 + bg[0], l1 = p1 + bg[1];
        float u0 = u[(size_t)node * 2], u1 = u[(size_t)node * 2 + 1];
        float gn0 = -logf(-logf(u0 + 1e-20f) + 1e-20f);
        float gn1 = -logf(-logf(u1 + 1e-20f) + 1e-20f);
        float a0 = l0 + gn0, a1 = l1 + gn1;
        float m = fmaxf(a0, a1);
        float e0 = expf(a0 - m), e1 = expf(a1 - m);
        float inv = 1.0f / (e0 + e1);
        float s0 = e0 * inv, s1 = e1 * inv;
        float h0 = (s0 >= s1) ? 1.0f : 0.0f;
        float h1 = 1.0f - h0;
        gender[(size_t)node * 2 + 0] = (h0 - s0) + s0;
        gender[(size_t)node * 2 + 1] = (h1 - s1) + s1;
        label[node] = pl + blc[0];
    }
}

// ---------------- HMMA helpers ------------------------------------------------
__device__ __forceinline__ void ldsm4(unsigned& r0, unsigned& r1, unsigned& r2,
                                      unsigned& r3, unsigned addr) {
    asm volatile("ldmatrix.sync.aligned.m8n8.x4.shared.b16 {%0,%1,%2,%3}, [%4];"
                 : "=r"(r0), "=r"(r1), "=r"(r2), "=r"(r3) : "r"(addr));
}
__device__ __forceinline__ void ldsm4t(unsigned& r0, unsigned& r1, unsigned& r2,
                                       unsigned& r3, unsigned addr) {
    asm volatile("ldmatrix.sync.aligned.m8n8.x4.trans.shared.b16 {%0,%1,%2,%3}, [%4];"
                 : "=r"(r0), "=r"(r1), "=r"(r2), "=r"(r3) : "r"(addr));
}
__device__ __forceinline__ void mma16816(float* d, const unsigned* a, const unsigned* b) {
    asm volatile("mma.sync.aligned.m16n8k16.row.col.f32.f16.f16.f32 "
                 "{%0,%1,%2,%3}, {%4,%5,%6,%7}, {%8,%9}, {%0,%1,%2,%3};"
                 : "+f"(d[0]), "+f"(d[1]), "+f"(d[2]), "+f"(d[3])
                 : "r"(a[0]), "r"(a[1]), "r"(a[2]), "r"(a[3]), "r"(b[0]), "r"(b[1]));
}

// ---------------- HMMA GEMM: A fp32 @ B fp16; fp32 C and/or fp16 Ch ----------
__global__ __launch_bounds__(256) void hgemm128(
    const float* __restrict__ A, const __half* __restrict__ Bh,
    const float* __restrict__ bias, float* __restrict__ C,
    __half* __restrict__ Ch, int N, int K)
{
    __shared__ __half sAh[128][24];
    __shared__ __half sBh[16][136];

    int tid = threadIdx.x;
    int lane = tid & 31;
    int wid = tid >> 5;
    int wm = (wid & 3) * 32;
    int wn = (wid >> 2) * 64;
    int row0 = blockIdx.y * 128;

    float acc[2][8][4];
#pragma unroll
    for (int i = 0; i < 2; i++)
#pragma unroll
        for (int j = 0; j < 8; j++)
#pragma unroll
            for (int k = 0; k < 4; k++) acc[i][j][k] = 0.f;

    int ar = tid >> 1, ak = (tid & 1) * 8;
    int br = tid & 15, bc = (tid >> 4) * 8;

    unsigned sa_base = (unsigned)__cvta_generic_to_shared(&sAh[0][0]);
    unsigned sb_base = (unsigned)__cvta_generic_to_shared(&sBh[0][0]);

    const int KSTEPS = K >> 4;
    for (int ks = 0; ks < KSTEPS; ks++) {
        int k0 = ks << 4;
        float va[8] = {0, 0, 0, 0, 0, 0, 0, 0};
        if (row0 + ar < N) {
            const float* ap = A + (size_t)(row0 + ar) * K + k0 + ak;
            float4 f0 = *reinterpret_cast<const float4*>(ap);
            float4 f1 = *reinterpret_cast<const float4*>(ap + 4);
            va[0] = f0.x; va[1] = f0.y; va[2] = f0.z; va[3] = f0.w;
            va[4] = f1.x; va[5] = f1.y; va[6] = f1.z; va[7] = f1.w;
        }
        __half hh[8];
#pragma unroll
        for (int i = 0; i < 8; i++) hh[i] = __float2half_rn(va[i]);
        *reinterpret_cast<uint4*>(&sAh[ar][ak]) = *reinterpret_cast<uint4*>(hh);
        *reinterpret_cast<uint4*>(&sBh[br][bc]) =
            *reinterpret_cast<const uint4*>(Bh + (size_t)(k0 + br) * 128 + bc);
        __syncthreads();

        unsigned afh[2][4];
        int fr = lane & 15;
        int fc = (lane >> 4) * 8;
#pragma unroll
        for (int am = 0; am < 2; am++) {
            unsigned off = (unsigned)(((wm + am * 16 + fr) * 24 + fc) << 1);
            ldsm4(afh[am][0], afh[am][1], afh[am][2], afh[am][3], sa_base + off);
        }
        unsigned bfh[8][2];
#pragma unroll
        for (int bn = 0; bn < 4; bn++) {
            unsigned off = (unsigned)((fr * 136 + wn + bn * 16 + fc) << 1);
            ldsm4t(bfh[bn * 2][0], bfh[bn * 2][1], bfh[bn * 2 + 1][0], bfh[bn * 2 + 1][1],
                   sb_base + off);
        }
#pragma unroll
        for (int am = 0; am < 2; am++)
#pragma unroll
            for (int an = 0; an < 8; an++)
                mma16816(acc[am][an], afh[am], bfh[an]);
        __syncthreads();
    }

#pragma unroll
    for (int am = 0; am < 2; am++) {
        int rr = row0 + wm + am * 16 + (lane >> 2);
#pragma unroll
        for (int an = 0; an < 8; an++) {
            int cc = wn + an * 8 + (lane & 3) * 2;
            float bv0 = bias ? __ldg(bias + cc) : 0.f;
            float bv1 = bias ? __ldg(bias + cc + 1) : 0.f;
            if (rr < N) {
                float v0 = acc[am][an][0] + bv0, v1 = acc[am][an][1] + bv1;
                if (C) *reinterpret_cast<float2*>(C + (size_t)rr * 128 + cc) = make_float2(v0, v1);
                if (Ch) *reinterpret_cast<__half2*>(Ch + (size_t)rr * 128 + cc) = __floats2half2_rn(v0, v1);
            }
            if (rr + 8 < N) {
                float v2 = acc[am][an][2] + bv0, v3 = acc[am][an][3] + bv1;
                if (C) *reinterpret_cast<float2*>(C + (size_t)(rr + 8) * 128 + cc) = make_float2(v2, v3);
                if (Ch) *reinterpret_cast<__half2*>(Ch + (size_t)(rr + 8) * 128 + cc) = __floats2half2_rn(v2, v3);
            }
        }
    }
}

// ---------------- HMMA GEMM: hp' = (h @ [Wmu|Wls]) * dinv[row], fp16 A/B ----
__global__ __launch_bounds__(256) void hgemm_hh(
    const __half* __restrict__ A, const __half* __restrict__ Bh,
    __half* __restrict__ Chp, int N)
{
    const int K = 128;
    __shared__ __half sAh[128][24];
    __shared__ __half sBh[16][136];

    int tid = threadIdx.x;
    int lane = tid & 31;
    int wid = tid >> 5;
    int wm = (wid & 3) * 32;
    int wn = (wid >> 2) * 64;
    int row0 = blockIdx.y * 128;

    float acc[2][8][4];
#pragma unroll
    for (int i = 0; i < 2; i++)
#pragma unroll
        for (int j = 0; j < 8; j++)
#pragma unroll
            for (int k = 0; k < 4; k++) acc[i][j][k] = 0.f;

    int ar = tid >> 1, ak = (tid & 1) * 8;
    int br = tid & 15, bc = (tid >> 4) * 8;

    unsigned sa_base = (unsigned)__cvta_generic_to_shared(&sAh[0][0]);
    unsigned sb_base = (unsigned)__cvta_generic_to_shared(&sBh[0][0]);

    for (int ks = 0; ks < 8; ks++) {
        int k0 = ks << 4;
        uint4 av = make_uint4(0, 0, 0, 0);
        if (row0 + ar < N)
            av = *reinterpret_cast<const uint4*>(A + (size_t)(row0 + ar) * K + k0 + ak);
        *reinterpret_cast<uint4*>(&sAh[ar][ak]) = av;
        *reinterpret_cast<uint4*>(&sBh[br][bc]) =
            *reinterpret_cast<const uint4*>(Bh + (size_t)(k0 + br) * 128 + bc);
        __syncthreads();

        unsigned afh[2][4];
        int fr = lane & 15;
        int fc = (lane >> 4) * 8;
#pragma unroll
        for (int am = 0; am < 2; am++) {
            unsigned off = (unsigned)(((wm + am * 16 + fr) * 24 + fc) << 1);
            ldsm4(afh[am][0], afh[am][1], afh[am][2], afh[am][3], sa_base + off);
        }
        unsigned bfh[8][2];
#pragma unroll
        for (int bn = 0; bn < 4; bn++) {
            unsigned off = (unsigned)((fr * 136 + wn + bn * 16 + fc) << 1);
            ldsm4t(bfh[bn * 2][0], bfh[bn * 2][1], bfh[bn * 2 + 1][0], bfh[bn * 2 + 1][1],
                   sb_base + off);
        }
#pragma unroll
        for (int am = 0; am < 2; am++)
#pragma unroll
            for (int an = 0; an < 8; an++)
                mma16816(acc[am][an], afh[am], bfh[an]);
        __syncthreads();
    }

#pragma unroll
    for (int am = 0; am < 2; am++) {
        int rr = row0 + wm + am * 16 + (lane >> 2);
        float s0 = (rr < N) ? node_dinv(rr) : 1.f;
        float s1 = (rr + 8 < N) ? node_dinv(rr + 8) : 1.f;
#pragma unroll
        for (int an = 0; an < 8; an++) {
            int cc = wn + an * 8 + (lane & 3) * 2;
            if (rr < N)
                *reinterpret_cast<__half2*>(Chp + (size_t)rr * 128 + cc) =
                    __floats2half2_rn(acc[am][an][0] * s0, acc[am][an][1] * s0);
            if (rr + 8 < N)
                *reinterpret_cast<__half2*>(Chp + (size_t)(rr + 8) * 128 + cc) =
                    __floats2half2_rn(acc[am][an][2] * s1, acc[am][an][3] * s1);
        }
    }
}

// ---------------- launch -----------------------------------------------------
extern "C" void kernel_launch(void* const* d_in, const int* in_sizes, int n_in,
                              void* d_out, int out_size) {
    const float* x   = (const float*)d_in[0];
    const int*   ei  = (const int*)d_in[1];
    const float* eps = (const float*)d_in[2];
    const float* u   = (const float*)d_in[3];
    const float* W1  = (const float*)d_in[4];
    const float* b1  = (const float*)d_in[5];
    const float* Wmu = (const float*)d_in[6];
    const float* bmu = (const float*)d_in[7];
    const float* Wls = (const float*)d_in[8];
    const float* bls = (const float*)d_in[9];
    const float* Wdx = (const float*)d_in[10];
    const float* bdx = (const float*)d_in[11];
    const float* Wg  = (const float*)d_in[12];
    const float* bg  = (const float*)d_in[13];
    const float* Wlc = (const float*)d_in[14];
    const float* blc = (const float*)d_in[15];

    const int N = in_sizes[0] / 128;
    const int E = in_sizes[1] / 2;
    const int* src = ei;
    const int* dst = ei + E;

    float* out    = (float*)d_out;
    float* recon  = out;                     // [N,128]
    float* gender = out + (size_t)N * 128;   // [N,2]
    float* label  = gender + (size_t)N * 2;  // [N,1]
    float* mu     = label + N;               // [N,64]
    float* lv     = mu + (size_t)N * 64;     // [N,64]
    float* z      = lv + (size_t)N * 64;     // [N,64]

    float *p_az;
    __half *p_tb, *p_hb, *p_zh, *p_w1h, *p_wdxh, *p_wph;
    int *p_cur;
    cudaGetSymbolAddress((void**)&p_tb, g_tb);
    cudaGetSymbolAddress((void**)&p_hb, g_hb);
    cudaGetSymbolAddress((void**)&p_zh, g_zh);
    cudaGetSymbolAddress((void**)&p_az, g_az);
    cudaGetSymbolAddress((void**)&p_w1h, g_w1h);
    cudaGetSymbolAddress((void**)&p_wdxh, g_wdxh);
    cudaGetSymbolAddress((void**)&p_wph, g_wph);
    cudaGetSymbolAddress((void**)&p_cur, g_cur);

    // persistent side stream / events for graph-parallel branch
    static cudaStream_t s1 = nullptr;
    static cudaEvent_t evRoot = nullptr, evW = nullptr;
    if (!s1) {
        cudaStreamCreateWithFlags(&s1, cudaStreamNonBlocking);
        cudaEventCreateWithFlags(&evRoot, cudaEventDisableTiming);
        cudaEventCreateWithFlags(&evW, cudaEventDisableTiming);
    }

    const int T = 256;
    int nodeWarpBlocks = (int)(((size_t)N * 32 + T - 1) / T);
    int e4Blocks = ((E + 3) / 4 + T - 1) / T;
    dim3 gg(1, (N + 127) / 128);

    // ---- fork: weights + unscaled t-GEMM parallel to bucket fill ----
    cudaEventRecord(evRoot, 0);
    cudaStreamWaitEvent(s1, evRoot, 0);
    cvt_weights<<<(128 * 128 + T - 1) / T, T, 0, s1>>>(W1, Wdx, Wmu, Wls, bmu, bls);
    hgemm128<<<gg, 256, 0, s1>>>(x, p_w1h, nullptr, nullptr, p_tb, N, 128);
    cudaEventRecord(evW, s1);

    // ---- main stream: one-pass bucket CSR ----
    cudaMemsetAsync(p_cur, 0, (size_t)N * CPAD * sizeof(int), 0);
    bucket_fill<<<e4Blocks, T>>>(src, dst, E);

    // ---- join; t' = t * dinv ----
    cudaStreamWaitEvent(0, evW, 0);
    scale_t<<<(N * 16 + T - 1) / T, T>>>(p_tb, N);

    // h = relu(dinv * (A-sum of t') + b1)
    agg_h<<<nodeWarpBlocks, T>>>(p_tb, p_hb, b1, N);

    // hp' = (h @ [Wmu|Wls]) * dinv  (fp16 table, reuses g_tb)
    hgemm_hh<<<gg, 256>>>(p_hb, p_wph, p_tb, N);

    // [mu|lv] = dinv * (A-sum of hp') + b; z; z' table
    agg_z<<<nodeWarpBlocks, T>>>(p_tb, eps, mu, lv, z, p_zh, N);

    // az = dinv * (A-sum of z'); fused gender/label heads
    agg64_heads<<<nodeWarpBlocks, T>>>(p_zh, z, u, Wg, bg, Wlc, blc,
                                       p_az, gender, label, N);

    // recon_x = az @ Wdx + bdx
    hgemm128<<<gg, 256>>>(p_az, p_wdxh, bdx, recon, nullptr, N, 64);
}